// round 1
// baseline (speedup 1.0000x reference)
#include <cuda_runtime.h>
#include <cuda_bf16.h>

// SGNS: out[b] = [1-s, s], s = sigmoid( sum_w (W1[w,i1]+b1[w]) * (W2[w,i2]+b2[w]) )
// W1, W2: [128, 100000] row-major f32. idx1, idx2: [4096] int32.
// One warp per batch element; each lane covers 4 w-positions (w = lane + 32k).
// All 8 gather loads are independent -> issued back-to-back for max MLP.

#define D_DIM 100000
#define W_DIM 128
#define BATCH 4096

__global__ __launch_bounds__(256) void sgns_kernel(
    const int* __restrict__ idx1,
    const int* __restrict__ idx2,
    const float* __restrict__ W1,
    const float* __restrict__ b1,
    const float* __restrict__ W2,
    const float* __restrict__ b2,
    float* __restrict__ out)
{
    const int warp = (blockIdx.x * blockDim.x + threadIdx.x) >> 5;
    const int lane = threadIdx.x & 31;
    if (warp >= BATCH) return;

    // Broadcast loads (same address across warp -> single sector)
    const long long i1 = idx1[warp];
    const long long i2 = idx2[warp];

    // Issue all 8 gather loads up front (independent, strided by 32*D_DIM).
    float a0, a1, a2, a3, c0, c1, c2, c3;
    {
        const float* p1 = W1 + (long long)lane * D_DIM + i1;
        const float* p2 = W2 + (long long)lane * D_DIM + i2;
        a0 = __ldg(p1 + 0LL  * 32 * D_DIM);
        a1 = __ldg(p1 + 1LL  * 32 * D_DIM);
        a2 = __ldg(p1 + 2LL  * 32 * D_DIM);
        a3 = __ldg(p1 + 3LL  * 32 * D_DIM);
        c0 = __ldg(p2 + 0LL  * 32 * D_DIM);
        c1 = __ldg(p2 + 1LL  * 32 * D_DIM);
        c2 = __ldg(p2 + 2LL  * 32 * D_DIM);
        c3 = __ldg(p2 + 3LL  * 32 * D_DIM);
    }

    // Bias loads: tiny arrays, broadcast-friendly.
    const float e0 = b1[lane +  0], e1 = b1[lane + 32],
                e2 = b1[lane + 64], e3 = b1[lane + 96];
    const float f0 = b2[lane +  0], f1 = b2[lane + 32],
                f2 = b2[lane + 64], f3 = b2[lane + 96];

    float acc = (a0 + e0) * (c0 + f0)
              + (a1 + e1) * (c1 + f1)
              + (a2 + e2) * (c2 + f2)
              + (a3 + e3) * (c3 + f3);

    // Warp reduction over 32 lanes (each already holds 4 w-terms).
    #pragma unroll
    for (int off = 16; off > 0; off >>= 1)
        acc += __shfl_xor_sync(0xFFFFFFFFu, acc, off);

    if (lane == 0) {
        const float s = 1.0f / (1.0f + expf(-acc));
        out[2 * warp + 0] = 1.0f - s;
        out[2 * warp + 1] = s;
    }
}

extern "C" void kernel_launch(void* const* d_in, const int* in_sizes, int n_in,
                              void* d_out, int out_size)
{
    const int*   idx1 = (const int*)  d_in[0];
    const int*   idx2 = (const int*)  d_in[1];
    const float* W1   = (const float*)d_in[2];
    const float* b1   = (const float*)d_in[3];
    const float* W2   = (const float*)d_in[4];
    const float* b2   = (const float*)d_in[5];
    float* out = (float*)d_out;

    // 4096 warps, 8 warps per 256-thread block -> 512 blocks.
    sgns_kernel<<<BATCH / 8, 256>>>(idx1, idx2, W1, b1, W2, b2, out);
}